// round 14
// baseline (speedup 1.0000x reference)
#include <cuda_runtime.h>
#include <math.h>

#define BATCH 64
#define SEQ   2048
#define DIN   256
#define DOUT  256
#define MTOT  (BATCH * SEQ)

#define NSCAN   64
#define NWORK   84
#define NCTA    (NSCAN + NWORK)      // 148 CTAs = one per SM
#define CHUNK   64
#define NCHUNK  (SEQ / CHUNK)        // 32
#define NTILES  (NCHUNK * BATCH * 4) // 8192 64x64 tiles, time-ordered

#define KREG 176
#define NGR  (KREG / 4)              // 44 register-weight groups
#define KSM  (DOUT - KREG)           // 80
#define NGT  (KSM / 4)               // 20 L1-table weight groups

// gemm needs 4416 floats; scan needs 512. Take max.
#define SMEM_BYTES ((64 * 36 + 32 * 64 + 64) * (int)sizeof(float))  // 17664

__device__ int   g_flags[BATCH * NCHUNK];
// weight tail, layout [g][j][4]: g_WhT2[g*1024 + j*4 + i] = Wh[(KREG+4g+i)*256 + j]
// -> lanes of a warp read consecutive 16B chunks (4 wavefronts per LDG.128).
__device__ float g_WhT2[NGT * 1024];   // 80 KB, L1-resident on scan SMs

__global__ void prep_kernel(const float* __restrict__ Wh)
{
    int i = blockIdx.x * blockDim.x + threadIdx.x;
    if (i < BATCH * NCHUNK) g_flags[i] = 0;
    for (int e = i; e < NGT * 1024; e += gridDim.x * blockDim.x) {
        int g  = e >> 10;
        int r  = e & 1023;
        int jj = r >> 2;
        int ii = r & 3;
        g_WhT2[e] = Wh[(KREG + 4 * g + ii) * DOUT + jj];
    }
}

__device__ __forceinline__ int ld_acquire_gpu(const int* p)
{
    int v;
    asm volatile("ld.acquire.gpu.global.b32 %0, [%1];"
                 : "=r"(v) : "l"(p) : "memory");
    return v;
}

// Pinned (volatile) non-coherent 128-bit global load: ptxas cannot hoist or
// batch these, so the depth-3 rotation below never inflates register pressure.
__device__ __forceinline__ float4 ldg_pin(const float4* p)
{
    float4 v;
    asm volatile("ld.global.nc.v4.f32 {%0,%1,%2,%3}, [%4];"
                 : "=f"(v.x), "=f"(v.y), "=f"(v.z), "=f"(v.w)
                 : "l"(p));
    return v;
}

// ---------------------------------------------------------------------------
// Bit-exact replica of XLA's EmitFastTanh (Eigen fast tanh, FMA variant).
// ---------------------------------------------------------------------------
__device__ __forceinline__ float xla_tanh(float x)
{
    const float kClamp = 7.99881172180175781f;
    const float kTiny  = 0.0004f;
    const float a1  = 4.89352455891786e-03f;
    const float a3  = 6.37261928875436e-04f;
    const float a5  = 1.48572235717979e-05f;
    const float a7  = 5.12229709037114e-08f;
    const float a9  = -8.60467152213735e-11f;
    const float a11 = 2.00018790482477e-13f;
    const float a13 = -2.76076847742355e-16f;
    const float b0  = 4.89352518554385e-03f;
    const float b2  = 2.26843463243900e-03f;
    const float b4  = 1.18534705686654e-04f;
    const float b6  = 1.19825839466702e-06f;

    float ax = fabsf(x);
    float xc = fminf(fmaxf(x, -kClamp), kClamp);
    float x2 = __fmul_rn(xc, xc);

    float p = __fmaf_rn(x2, a13, a11);
    p = __fmaf_rn(x2, p, a9);
    p = __fmaf_rn(x2, p, a7);
    p = __fmaf_rn(x2, p, a5);
    p = __fmaf_rn(x2, p, a3);
    p = __fmaf_rn(x2, p, a1);
    p = __fmul_rn(xc, p);

    float q = __fmaf_rn(x2, b6, b4);
    q = __fmaf_rn(x2, q, b2);
    q = __fmaf_rn(x2, q, b0);

    float r = __fdiv_rn(p, q);
    return (ax < kTiny) ? x : r;
}

// ---------------------------------------------------------------------------
// GEMM producer: zx = input @ W_x + (b_x+b_h), 64x64 tiles in time order.
// Bit-exact: single fp32 accumulator, ascending k, fused FMA.
// ---------------------------------------------------------------------------
__device__ void gemm_worker(
    float* sm, int worker,
    const float* __restrict__ A,
    const float* __restrict__ W,
    const float* __restrict__ b_h,
    const float* __restrict__ b_x,
    float* __restrict__ C)
{
    float* As   = sm;                // [64][36]
    float* Bs   = sm + 64 * 36;      // [32][64]
    float* bias = sm + 64 * 36 + 32 * 64;

    const int tid = threadIdx.x;
    const int tx = tid & 15;
    const int ty = tid >> 4;

    for (int tau = worker; tau < NTILES; tau += NWORK) {
        const int c  = tau >> 8;
        const int r  = tau & 255;
        const int bb = r >> 2;
        const int nq = r & 3;
        const long m0 = (long)bb * SEQ + (long)c * CHUNK;
        const int n0 = nq * 64;

        if (tid < 64) bias[tid] = __fadd_rn(b_h[n0 + tid], b_x[n0 + tid]);

        float acc[16];
#pragma unroll
        for (int i = 0; i < 16; ++i) acc[i] = 0.f;

        for (int kc = 0; kc < DIN; kc += 32) {
            __syncthreads();
            {
                int i0 = tid, i1 = tid + 256;
                int r0 = i0 >> 3, c0 = (i0 & 7) << 2;
                int r1 = i1 >> 3, c1 = (i1 & 7) << 2;
                float4 v0 = __ldcs((const float4*)(A + (m0 + r0) * DIN + kc + c0));
                float4 v1 = __ldcs((const float4*)(A + (m0 + r1) * DIN + kc + c1));
                As[r0 * 36 + c0 + 0] = v0.x; As[r0 * 36 + c0 + 1] = v0.y;
                As[r0 * 36 + c0 + 2] = v0.z; As[r0 * 36 + c0 + 3] = v0.w;
                As[r1 * 36 + c1 + 0] = v1.x; As[r1 * 36 + c1 + 1] = v1.y;
                As[r1 * 36 + c1 + 2] = v1.z; As[r1 * 36 + c1 + 3] = v1.w;
            }
            {
                int i0 = tid, i1 = tid + 256;
                int k0 = i0 >> 4, g0 = (i0 & 15) << 2;
                int k1 = i1 >> 4, g1 = (i1 & 15) << 2;
                *(float4*)(Bs + k0 * 64 + g0) =
                    *(const float4*)(W + (kc + k0) * DOUT + n0 + g0);
                *(float4*)(Bs + k1 * 64 + g1) =
                    *(const float4*)(W + (kc + k1) * DOUT + n0 + g1);
            }
            __syncthreads();

#pragma unroll
            for (int k = 0; k < 32; ++k) {
                float4 b4 = *(const float4*)(Bs + k * 64 + (tx << 2));
                float a0 = As[(ty * 4 + 0) * 36 + k];
                float a1 = As[(ty * 4 + 1) * 36 + k];
                float a2 = As[(ty * 4 + 2) * 36 + k];
                float a3 = As[(ty * 4 + 3) * 36 + k];
                acc[ 0] = __fmaf_rn(a0, b4.x, acc[ 0]);
                acc[ 1] = __fmaf_rn(a0, b4.y, acc[ 1]);
                acc[ 2] = __fmaf_rn(a0, b4.z, acc[ 2]);
                acc[ 3] = __fmaf_rn(a0, b4.w, acc[ 3]);
                acc[ 4] = __fmaf_rn(a1, b4.x, acc[ 4]);
                acc[ 5] = __fmaf_rn(a1, b4.y, acc[ 5]);
                acc[ 6] = __fmaf_rn(a1, b4.z, acc[ 6]);
                acc[ 7] = __fmaf_rn(a1, b4.w, acc[ 7]);
                acc[ 8] = __fmaf_rn(a2, b4.x, acc[ 8]);
                acc[ 9] = __fmaf_rn(a2, b4.y, acc[ 9]);
                acc[10] = __fmaf_rn(a2, b4.z, acc[10]);
                acc[11] = __fmaf_rn(a2, b4.w, acc[11]);
                acc[12] = __fmaf_rn(a3, b4.x, acc[12]);
                acc[13] = __fmaf_rn(a3, b4.y, acc[13]);
                acc[14] = __fmaf_rn(a3, b4.z, acc[14]);
                acc[15] = __fmaf_rn(a3, b4.w, acc[15]);
            }
        }

#pragma unroll
        for (int i = 0; i < 4; ++i) {
            float4 o;
            o.x = __fadd_rn(acc[i * 4 + 0], bias[(tx << 2) + 0]);
            o.y = __fadd_rn(acc[i * 4 + 1], bias[(tx << 2) + 1]);
            o.z = __fadd_rn(acc[i * 4 + 2], bias[(tx << 2) + 2]);
            o.w = __fadd_rn(acc[i * 4 + 3], bias[(tx << 2) + 3]);
            *(float4*)(C + (m0 + ty * 4 + i) * DOUT + n0 + (tx << 2)) = o;
        }

        __threadfence();
        __syncthreads();
        if (tid == 0) atomicAdd(&g_flags[bb * NCHUNK + c], 1);
    }
}

// ---------------------------------------------------------------------------
// One scan step. Chain: k 0..175 register weights, k 176..255 L1-table
// weights via pinned depth-3 LDG rotation. Single accumulator, ascending k.
// ---------------------------------------------------------------------------
__device__ __forceinline__ float scan_step(
    const float4* __restrict__ h4,
    const float* __restrict__ w,
    const float4* __restrict__ wbase,   // &g_WhT2[j*4] as float4*, group g at +256*g
    float zx)
{
    float acc = 0.f;

    // register-weight groups 0..41
#pragma unroll
    for (int g = 0; g < NGR - 2; ++g) {
        float4 hv = h4[g];
        acc = __fmaf_rn(hv.x, w[4 * g + 0], acc);
        acc = __fmaf_rn(hv.y, w[4 * g + 1], acc);
        acc = __fmaf_rn(hv.z, w[4 * g + 2], acc);
        acc = __fmaf_rn(hv.w, w[4 * g + 3], acc);
    }

    // prime depth-3 pipeline 2 groups (~32 cyc) before first use
    float4 q0 = ldg_pin(wbase + 0 * 256);
    float4 q1 = ldg_pin(wbase + 1 * 256);
    float4 q2 = ldg_pin(wbase + 2 * 256);

    // register-weight groups 42..43
#pragma unroll
    for (int g = NGR - 2; g < NGR; ++g) {
        float4 hv = h4[g];
        acc = __fmaf_rn(hv.x, w[4 * g + 0], acc);
        acc = __fmaf_rn(hv.y, w[4 * g + 1], acc);
        acc = __fmaf_rn(hv.z, w[4 * g + 2], acc);
        acc = __fmaf_rn(hv.w, w[4 * g + 3], acc);
    }

    // table groups 0..19 (k = 176..255)
#pragma unroll
    for (int g = 0; g < NGT; ++g) {
        float4 wv = (g % 3 == 0) ? q0 : (g % 3 == 1) ? q1 : q2;
        if (g + 3 < NGT) {                        // prefetch 3 groups ahead
            float4 nq = ldg_pin(wbase + (g + 3) * 256);
            if (g % 3 == 0) q0 = nq; else if (g % 3 == 1) q1 = nq; else q2 = nq;
        }
        float4 hv = h4[NGR + g];
        acc = __fmaf_rn(hv.x, wv.x, acc);
        acc = __fmaf_rn(hv.y, wv.y, acc);
        acc = __fmaf_rn(hv.z, wv.z, acc);
        acc = __fmaf_rn(hv.w, wv.w, acc);
    }

    return xla_tanh(__fadd_rn(acc, zx));
}

// ---------------------------------------------------------------------------
// Fused kernel. Scan CTAs [0,64): thread j owns column j; step loop unrolled
// by 2 with explicit ping/pong buffers; weight tail on the L1tex pipe.
// ---------------------------------------------------------------------------
__global__ __launch_bounds__(256, 1) void rnn_fused_kernel(
    const float* __restrict__ input,
    const float* __restrict__ h0,
    const float* __restrict__ Wh,
    const float* __restrict__ Wx,
    const float* __restrict__ b_h,
    const float* __restrict__ b_x,
    float* __restrict__ y,
    float* __restrict__ hfin)
{
    extern __shared__ float sm[];

    if (blockIdx.x >= NSCAN) {
        gemm_worker(sm, blockIdx.x - NSCAN, input, Wx, b_h, b_x, y);
        return;
    }

    float* hb0 = sm;              // [256]
    float* hb1 = sm + DOUT;       // [256]

    const int b = blockIdx.x;
    const int j = threadIdx.x;

    float w[KREG];
#pragma unroll
    for (int kk = 0; kk < KREG; ++kk)
        w[kk] = Wh[kk * DOUT + j];

    hb0[j] = h0[b * DOUT + j];

    float* yb = y + (size_t)b * SEQ * DOUT;
    const float4* wbase = (const float4*)g_WhT2 + j;   // group g at +256*g
    const float4* h40 = (const float4*)hb0;
    const float4* h41 = (const float4*)hb1;

    for (int c = 0; c < NCHUNK; ++c) {
        if (j == 0) {
            while (ld_acquire_gpu(&g_flags[b * NCHUNK + c]) != 4) { }
        }
        __syncthreads();              // chunk gate; also orders setup at c=0

#pragma unroll 1
        for (int ti = 0; ti < CHUNK; ti += 2) {
            const size_t t0 = (size_t)(c * CHUNK + ti) * DOUT + j;

            float zx0 = __ldcs(&yb[t0]);
            float zx1 = __ldcs(&yb[t0 + DOUT]);

            // step even: hb0 -> hb1
            float v0 = scan_step(h40, w, wbase, zx0);
            hb1[j] = v0;
            __stcs(&yb[t0], v0);
            __syncthreads();

            // step odd: hb1 -> hb0
            float v1 = scan_step(h41, w, wbase, zx1);
            hb0[j] = v1;
            __stcs(&yb[t0 + DOUT], v1);
            __syncthreads();
        }
    }

    hfin[b * DOUT + j] = hb0[j];      // SEQ even: final state in hb0
}

// ---------------------------------------------------------------------------
extern "C" void kernel_launch(void* const* d_in, const int* in_sizes, int n_in,
                              void* d_out, int out_size)
{
    const float* input = (const float*)d_in[0];
    const float* h0    = (const float*)d_in[1];
    const float* W_h   = (const float*)d_in[2];
    const float* W_x   = (const float*)d_in[3];
    const float* b_h   = (const float*)d_in[4];
    const float* b_x   = (const float*)d_in[5];

    float* y    = (float*)d_out;
    float* hfin = y + (size_t)BATCH * SEQ * DOUT;

    cudaFuncSetAttribute(rnn_fused_kernel,
                         cudaFuncAttributeMaxDynamicSharedMemorySize,
                         SMEM_BYTES);

    prep_kernel<<<32, 256>>>(W_h);
    rnn_fused_kernel<<<NCTA, 256, SMEM_BYTES>>>(
        input, h0, W_h, W_x, b_h, b_x, y, hfin);
}